// round 7
// baseline (speedup 1.0000x reference)
#include <cuda_runtime.h>
#include <cstdint>

// Problem constants
#define NN 128
#define CC 64
#define TT 256
#define VV 25
#define DD 64
#define RR 16            // SE reduction dim
#define FEAT 1600        // V*D
#define ROWS (NN*TT)     // 32768
#define TTILE 8          // frames per gemm tile
#define NTILES 4         // tiles per gemm block
#define VS 26            // padded v (pad slot zero)
#define TSTR (TTILE*VS)  // 208 floats per c-row per tile
#define TILE_F (CC*TSTR) // 13312 floats per tile buffer
#define STATW 1664       // stats staging stride per warp (25*66 <= 1664)

typedef unsigned long long u64;

// ---------------- scratch (device globals) -----------------------------------
__device__ float g_pooled[NN*CC];
__device__ float g_gate[NN*4];
__device__ float g_Wf[NN*CC*DD];
__device__ float g_bf[NN*DD];
__device__ float g_y[(size_t)ROWS*FEAT];   // 210 MB, y in [row][f=v*64+d] layout
__device__ float g_sum[FEAT];              // y-space stats
__device__ float g_sumsq[FEAT];
__device__ float g_scale[FEAT];            // z-space BN params
__device__ float g_bias[FEAT];
__device__ float g_tm2q[CC*200];           // mask factor in raw-read order
__device__ short g_dtab[CC*200];           // dst offset within c-row: t*26 + (v_in - c) mod 25

// ---------------- helpers ----------------------------------------------------
__device__ __forceinline__ u64 pack2(float lo, float hi) {
    u64 r; asm("mov.b64 %0, {%1, %2};" : "=l"(r) : "f"(lo), "f"(hi)); return r;
}
__device__ __forceinline__ void unpack2(u64 v, float& lo, float& hi) {
    asm("mov.b64 {%0, %1}, %2;" : "=f"(lo), "=f"(hi) : "l"(v));
}
__device__ __forceinline__ u64 ffma2(u64 a, u64 b, u64 c) {
    u64 d; asm("fma.rn.f32x2 %0, %1, %2, %3;" : "=l"(d) : "l"(a), "l"(b), "l"(c));
    return d;
}

// ---------------- kernel 0: tables + zero stats ------------------------------
__global__ void table_kernel(const float* __restrict__ mask) {
    int tid = blockIdx.x * 256 + threadIdx.x;    // grid 50 -> 12800
    if (tid < CC*200) {
        int c = tid / 200, idx = tid % 200;
        int t = idx / VV, v_in = idx % VV;
        int v_out = v_in - (c % VV); if (v_out < 0) v_out += VV;
        g_tm2q[tid] = tanhf(mask[v_out*CC + c]) + 1.0f;
        g_dtab[tid] = (short)(t*VS + v_out);
    }
    if (tid < FEAT) { g_sum[tid] = 0.f; g_sumsq[tid] = 0.f; }
}

// ---------------- kernel 1: global average pool ------------------------------
__global__ void pool_kernel(const float* __restrict__ x0) {
    int nc = blockIdx.x;
    const float4* p = (const float4*)(x0 + (size_t)nc * (TT*VV));
    float s = 0.f;
    for (int i = threadIdx.x; i < (TT*VV)/4; i += 256) {
        float4 v = p[i];
        s += v.x + v.y + v.z + v.w;
    }
    for (int off = 16; off > 0; off >>= 1) s += __shfl_down_sync(0xffffffffu, s, off);
    __shared__ float red[8];
    int w = threadIdx.x >> 5, l = threadIdx.x & 31;
    if (l == 0) red[w] = s;
    __syncthreads();
    if (threadIdx.x == 0) {
        float t = 0.f;
        #pragma unroll
        for (int i = 0; i < 8; i++) t += red[i];
        g_pooled[nc] = t * (1.f / (TT*VV));
    }
}

// ---------------- kernel 2: SE gate ------------------------------------------
__global__ void gate_kernel(const float* __restrict__ fc1_w, const float* __restrict__ fc1_b,
                            const float* __restrict__ fc2_w, const float* __restrict__ fc2_b,
                            const int* __restrict__ epoch_p) {
    int n = threadIdx.x;
    if (n >= NN) return;
    float pooled[CC];
    #pragma unroll
    for (int c = 0; c < CC; c++) pooled[c] = g_pooled[n*CC + c];
    float h[RR];
    #pragma unroll
    for (int j = 0; j < RR; j++) {
        float s = fc1_b[j];
        #pragma unroll
        for (int c = 0; c < CC; c++) s += pooled[c] * fc1_w[j*CC + c];
        h[j] = s > 0.f ? s : 0.f;
    }
    float lg[4];
    #pragma unroll
    for (int k = 0; k < 4; k++) {
        float s = fc2_b[k];
        #pragma unroll
        for (int j = 0; j < RR; j++) s += h[j] * fc2_w[k*RR + j];
        lg[k] = s;
    }
    int ep = *epoch_p;
    float tao = (ep >= 60) ? 1.0f : (-(29.0f / 60.0f) * (float)ep + 30.0f);
    float inv = 1.0f / tao;
    float m = lg[0];
    #pragma unroll
    for (int k = 1; k < 4; k++) m = fmaxf(m, lg[k]);
    float e[4], sum = 0.f;
    #pragma unroll
    for (int k = 0; k < 4; k++) { e[k] = __expf((lg[k] - m) * inv); sum += e[k]; }
    float r = 1.0f / sum;
    #pragma unroll
    for (int k = 0; k < 4; k++) g_gate[n*4 + k] = e[k] * r;
}

// ---------------- kernel 3: fused per-sample weights -------------------------
__global__ void prepw_kernel(const float* __restrict__ W, const float* __restrict__ b) {
    int n = blockIdx.x;
    int tid = threadIdx.x;
    float g0 = g_gate[n*4+0], g1 = g_gate[n*4+1], g2 = g_gate[n*4+2], g3 = g_gate[n*4+3];
    for (int i = tid; i < CC*DD; i += 256)
        g_Wf[n*CC*DD + i] = g0*W[i] + g1*W[CC*DD + i] + g2*W[2*CC*DD + i] + g3*W[3*CC*DD + i];
    if (tid < DD)
        g_bf[n*DD + tid] = g0*b[tid] + g1*b[DD+tid] + g2*b[2*DD+tid] + g3*b[3*DD+tid];
}

// ---------------- kernel 4: GEMM (rotated staging, dbl-buffer, fused stats) --
// 1024 blocks = (n, q8 of 32 frames); 4 tiles of 8 frames.
// 8 warps; warp = frame; lane = d-pair (2l, 2l+1), f32x2 over v-pairs.
#define GEMM_SMEM_BYTES (2*TILE_F*4)

__global__ void __launch_bounds__(256, 2) gemm_kernel(const float* __restrict__ x0) {
    extern __shared__ float sm[];
    float* buf0 = sm;                      // tile buffer A [c][t8][v26]
    float* buf1 = sm + TILE_F;             // tile buffer B

    int bid = blockIdx.x;
    int n = bid >> 3, q8 = bid & 7;
    int tid = threadIdx.x;
    int w = tid >> 5, l = tid & 31;
    int d0 = 2*l;

    // zero pad slots (v=25) of both buffers (pad only feeds discarded hi lane)
    for (int i = tid; i < CC*TTILE; i += 256) {
        int c = i >> 3, t = i & 7;
        buf0[c*TSTR + t*VS + VV] = 0.f;
        buf1[c*TSTR + t*VS + VV] = 0.f;
    }

    const float* xbase = x0 + (size_t)n * CC * (TT*VV) + (size_t)(q8*32) * VV;

    // stage tile 0 into buf0 (rotation + mask folded via tables)
    #pragma unroll
    for (int k = 0; k < 13; k++) {
        int i = tid + k*256;
        if (i < 3200) {
            int c = i / 50, q = i - c*50;
            float4 xv = *(const float4*)(xbase + (size_t)c*(TT*VV) + q*4);
            float4 mv = *(const float4*)(g_tm2q + c*200 + q*4);
            ushort4 dv = *(const ushort4*)(g_dtab + c*200 + q*4);
            float* rb = buf0 + c*TSTR;
            rb[dv.x] = xv.x*mv.x; rb[dv.y] = xv.y*mv.y;
            rb[dv.z] = xv.z*mv.z; rb[dv.w] = xv.w*mv.w;
        }
    }

    const float* Wg = g_Wf + (size_t)n * (CC*DD) + d0;
    float bias0 = g_bf[n*DD + d0], bias1 = g_bf[n*DD + d0 + 1];

    float rsum[7], rsq[7];
    #pragma unroll
    for (int k = 0; k < 7; k++) { rsum[k] = 0.f; rsq[k] = 0.f; }

    for (int it = 0; it < NTILES; it++) {
        float* cur = (it & 1) ? buf1 : buf0;
        float* nxt = (it & 1) ? buf0 : buf1;
        int t0 = q8*32 + it*TTILE;

        __syncthreads();                   // cur staged; prev stats consumed nxt

        // ---- FFMA2 mainloop ----
        u64 acc0[13], acc1[13];
        {
            u64 bb0 = pack2(bias0, bias0), bb1 = pack2(bias1, bias1);
            #pragma unroll
            for (int vp = 0; vp < 13; vp++) { acc0[vp] = bb0; acc1[vp] = bb1; }
        }
        const float* arow = cur + w*VS;
        #pragma unroll
        for (int cb = 0; cb < CC; cb += 4) {
            float2 wv[4];
            #pragma unroll
            for (int i = 0; i < 4; i++) wv[i] = *(const float2*)(Wg + (cb+i)*DD);
            #pragma unroll
            for (int i = 0; i < 4; i++) {
                u64 s0 = pack2(wv[i].x, wv[i].x);
                u64 s1 = pack2(wv[i].y, wv[i].y);
                const u64* ar = (const u64*)(arow + (cb+i)*TSTR);
                #pragma unroll
                for (int vp = 0; vp < 13; vp++) {
                    u64 a2 = ar[vp];
                    acc0[vp] = ffma2(a2, s0, acc0[vp]);
                    acc1[vp] = ffma2(a2, s1, acc1[vp]);
                }
            }
        }
        __syncthreads();                   // all reads of cur done

        // ---- y store (coalesced) + stats staging into cur (aliased) ----
        {
            float* yrow = g_y + (size_t)(n*TT + t0 + w) * FEAT + d0;
            float* stg = cur + w*STATW + d0;   // [v*66 + d]  (d0 offset: the R6 bug fix)
            #pragma unroll
            for (int vp = 0; vp < 13; vp++) {
                float a0, a1, c0, c1;
                unpack2(acc0[vp], a0, a1);
                unpack2(acc1[vp], c0, c1);
                int v = 2*vp;
                *(float2*)(yrow + v*DD) = make_float2(a0, c0);
                stg[v*66]     = a0;
                stg[v*66 + 1] = c0;
                if (v + 1 < VV) {
                    *(float2*)(yrow + (v+1)*DD) = make_float2(a1, c1);
                    stg[(v+1)*66]     = a1;
                    stg[(v+1)*66 + 1] = c1;
                }
            }
        }
        // ---- stage next tile into nxt ----
        if (it + 1 < NTILES) {
            const float* xb = xbase + (size_t)(it+1) * (TTILE*VV);
            #pragma unroll
            for (int k = 0; k < 13; k++) {
                int i = tid + k*256;
                if (i < 3200) {
                    int c = i / 50, q = i - c*50;
                    float4 xv = *(const float4*)(xb + (size_t)c*(TT*VV) + q*4);
                    float4 mv = *(const float4*)(g_tm2q + c*200 + q*4);
                    ushort4 dv = *(const ushort4*)(g_dtab + c*200 + q*4);
                    float* rb = nxt + c*TSTR;
                    rb[dv.x] = xv.x*mv.x; rb[dv.y] = xv.y*mv.y;
                    rb[dv.z] = xv.z*mv.z; rb[dv.w] = xv.w*mv.w;
                }
            }
        }
        __syncthreads();                   // stats staging visible

        // ---- stats: thread owns fixed f-slots over 8 warp regions ----
        #pragma unroll
        for (int k = 0; k < 7; k++) {
            int f = tid + k*256;
            if (f < FEAT) {
                int pa = (f >> 6) * 66 + (f & 63);
                float s = 0.f, q = 0.f;
                #pragma unroll
                for (int w8 = 0; w8 < 8; w8++) {
                    float v = cur[w8*STATW + pa];
                    s += v; q += v*v;
                }
                rsum[k] += s; rsq[k] += q;
            }
        }
        // loop-top sync protects cur (stats region) before it becomes nxt
    }
    __syncthreads();
    #pragma unroll
    for (int k = 0; k < 7; k++) {
        int f = tid + k*256;
        if (f < FEAT) {
            atomicAdd(&g_sum[f], rsum[k]);
            atomicAdd(&g_sumsq[f], rsq[k]);
        }
    }
}

// ---------------- kernel 5: finalize BN params (permute y-stats to z-space) --
__global__ void finalize_kernel(const int* __restrict__ shift_out,
                                const float* __restrict__ gamma,
                                const float* __restrict__ beta) {
    int f = blockIdx.x * 256 + threadIdx.x;
    if (f >= FEAT) return;
    int s = shift_out[f];
    const float invn = 1.0f / (float)ROWS;
    float mu = g_sum[s] * invn;
    float var = g_sumsq[s] * invn - mu * mu;
    float sc = gamma[f] * rsqrtf(var + 1e-5f);
    g_scale[f] = sc;
    g_bias[f] = beta[f] - mu * sc;
}

// ---------------- kernel 6: shift-out + BN + residual + relu + transpose -----
#define ZSTRIDE 1632
#define FINAL_SMEM_BYTES ((TTILE*FEAT + 4*ZSTRIDE)*4)
__global__ void __launch_bounds__(256, 2) final_kernel(const float* __restrict__ x0,
                                                       const int* __restrict__ shift_out,
                                                       float* __restrict__ out) {
    extern __shared__ float fs[];
    float* ysm = fs;                      // 8 x 1600
    float* zsm = fs + TTILE*FEAT;         // 4 x 1632 (v*65+d layout)

    int bid = blockIdx.x;
    int n  = bid >> 5;
    int t0 = (bid & 31) * TTILE;
    int tid = threadIdx.x;

    {
        const float4* ys = (const float4*)(g_y + (size_t)(n*TT + t0) * FEAT);
        float4* yd = (float4*)ysm;
        for (int i = tid; i < (TTILE*FEAT)/4; i += 256) yd[i] = ys[i];
    }
    __syncthreads();

    size_t nbase = (size_t)n * CC * (TT*VV);
    #pragma unroll
    for (int half = 0; half < 2; half++) {
        #pragma unroll
        for (int tl = 0; tl < 4; tl++) {
            const float* yr = ysm + (half*4 + tl)*FEAT;
            for (int f = tid; f < FEAT; f += 256) {
                int v = f >> 6, d = f & 63;
                float val = yr[shift_out[f]] * g_scale[f] + g_bias[f];
                zsm[tl*ZSTRIDE + v*65 + d] = val;
            }
        }
        __syncthreads();
        for (int e = tid; e < 4*FEAT; e += 256) {
            int d = e / 100;
            int r = e - d * 100;
            int tl = r / 25;
            int v = r - tl * 25;
            float z = zsm[tl*ZSTRIDE + v*65 + d];
            size_t idx = nbase + (size_t)d * (TT*VV) + (size_t)(t0 + half*4 + tl) * VV + v;
            float o = z + x0[idx];
            out[idx] = o > 0.f ? o : 0.f;
        }
        __syncthreads();
    }
}

// ---------------- launcher ---------------------------------------------------
extern "C" void kernel_launch(void* const* d_in, const int* in_sizes, int n_in,
                              void* d_out, int out_size) {
    const float* x0       = (const float*)d_in[0];
    const int*   epoch    = (const int*)  d_in[1];
    const float* fc1_w    = (const float*)d_in[2];
    const float* fc1_b    = (const float*)d_in[3];
    const float* fc2_w    = (const float*)d_in[4];
    const float* fc2_b    = (const float*)d_in[5];
    const float* W        = (const float*)d_in[6];
    const float* b        = (const float*)d_in[7];
    const float* mask     = (const float*)d_in[8];
    const float* gamma    = (const float*)d_in[9];
    const float* beta     = (const float*)d_in[10];
    const int*   shift_in = (const int*)  d_in[11];  // unused (rotation derived analytically)
    const int*   shift_out= (const int*)  d_in[12];
    float* out = (float*)d_out;
    (void)shift_in;

    cudaFuncSetAttribute(gemm_kernel, cudaFuncAttributeMaxDynamicSharedMemorySize, GEMM_SMEM_BYTES);
    cudaFuncSetAttribute(final_kernel, cudaFuncAttributeMaxDynamicSharedMemorySize, FINAL_SMEM_BYTES);

    table_kernel<<<50, 256>>>(mask);
    pool_kernel<<<NN*CC, 256>>>(x0);
    gate_kernel<<<1, 128>>>(fc1_w, fc1_b, fc2_w, fc2_b, epoch);
    prepw_kernel<<<NN, 256>>>(W, b);
    gemm_kernel<<<NN*8, 256, GEMM_SMEM_BYTES>>>(x0);
    finalize_kernel<<<(FEAT + 255)/256, 256>>>(shift_out, gamma, beta);
    final_kernel<<<NN*(TT/TTILE), 256, FINAL_SMEM_BYTES>>>(x0, shift_out, out);
}

// round 8
// speedup vs baseline: 1.3489x; 1.3489x over previous
#include <cuda_runtime.h>
#include <cstdint>

// Problem constants
#define NN 128
#define CC 64
#define TT 256
#define VV 25
#define DD 64
#define RR 16           // SE reduction dim (C/4)
#define FEAT 1600       // V*D
#define ROWS (NN*TT)    // 32768
#define TTILE 8         // t-frames per gemm tile
#define NTILES 4        // tiles per block
#define ATSTRIDE 26     // v-dim stride in At (26 floats = 104B, 8B-aligned rows)
#define ATW (CC*ATSTRIDE)   // 1664 floats per warp region

typedef unsigned long long u64;

// ---------------- scratch (device globals; no allocations allowed) ----------
__device__ float g_pooled[NN*CC];
__device__ float g_gate[NN*4];
__device__ float g_Wf[NN*CC*DD];      // 2 MB
__device__ float g_bf[NN*DD];
__device__ float g_z[(size_t)NN*CC*TT*VV]; // 209.7 MB, OUTPUT layout [n][d][t][v], pre-BN
__device__ float g_sum[FEAT];
__device__ float g_sumsq[FEAT];
__device__ float g_scale[FEAT];
__device__ float g_bias[FEAT];
__device__ short g_tsrc[CC*ATSTRIDE];  // gather table into raw smem tile
__device__ float g_tm[CC*ATSTRIDE];    // tanh(mask)+1, 0 on pad slots
__device__ short g_inv[FEAT];          // inv_pad: s -> f+(f>>6)  (= v*65+d)

// ---------------- f32x2 helpers ---------------------------------------------
__device__ __forceinline__ u64 pack2(float lo, float hi) {
    u64 r; asm("mov.b64 %0, {%1, %2};" : "=l"(r) : "f"(lo), "f"(hi)); return r;
}
__device__ __forceinline__ void unpack2(u64 v, float& lo, float& hi) {
    asm("mov.b64 {%0, %1}, %2;" : "=f"(lo), "=f"(hi) : "l"(v));
}
__device__ __forceinline__ u64 ffma2(u64 a, u64 b, u64 c) {
    u64 d; asm("fma.rn.f32x2 %0, %1, %2, %3;" : "=l"(d) : "l"(a), "l"(b), "l"(c));
    return d;
}
__device__ __forceinline__ void cp_async16(float* dst_smem, const void* src) {
    unsigned d = (unsigned)__cvta_generic_to_shared(dst_smem);
    asm volatile("cp.async.cg.shared.global [%0], [%1], 16;" :: "r"(d), "l"(src));
}
#define CP_COMMIT() asm volatile("cp.async.commit_group;")
#define CP_WAIT0()  asm volatile("cp.async.wait_group 0;")

// ---------------- kernel 1: global average pool ------------------------------
__global__ void pool_kernel(const float* __restrict__ x0) {
    int nc = blockIdx.x;
    const float4* p = (const float4*)(x0 + (size_t)nc * (TT*VV));
    float s = 0.f;
    for (int i = threadIdx.x; i < (TT*VV)/4; i += 256) {
        float4 v = p[i];
        s += v.x + v.y + v.z + v.w;
    }
    for (int off = 16; off > 0; off >>= 1) s += __shfl_down_sync(0xffffffffu, s, off);
    __shared__ float red[8];
    int w = threadIdx.x >> 5, l = threadIdx.x & 31;
    if (l == 0) red[w] = s;
    __syncthreads();
    if (threadIdx.x == 0) {
        float t = 0.f;
        #pragma unroll
        for (int i = 0; i < 8; i++) t += red[i];
        g_pooled[nc] = t * (1.f / (TT*VV));
    }
}

// ---------------- kernel 2: SE gate ------------------------------------------
__global__ void gate_kernel(const float* __restrict__ fc1_w, const float* __restrict__ fc1_b,
                            const float* __restrict__ fc2_w, const float* __restrict__ fc2_b,
                            const int* __restrict__ epoch_p) {
    int n = threadIdx.x;
    if (n >= NN) return;
    float pooled[CC];
    #pragma unroll
    for (int c = 0; c < CC; c++) pooled[c] = g_pooled[n*CC + c];
    float h[RR];
    #pragma unroll
    for (int j = 0; j < RR; j++) {
        float s = fc1_b[j];
        #pragma unroll
        for (int c = 0; c < CC; c++) s += pooled[c] * fc1_w[j*CC + c];
        h[j] = s > 0.f ? s : 0.f;
    }
    float lg[4];
    #pragma unroll
    for (int k = 0; k < 4; k++) {
        float s = fc2_b[k];
        #pragma unroll
        for (int j = 0; j < RR; j++) s += h[j] * fc2_w[k*RR + j];
        lg[k] = s;
    }
    int ep = *epoch_p;
    float tao = (ep >= 60) ? 1.0f : (-(29.0f / 60.0f) * (float)ep + 30.0f);
    float inv = 1.0f / tao;
    float m = lg[0];
    #pragma unroll
    for (int k = 1; k < 4; k++) m = fmaxf(m, lg[k]);
    float e[4], sum = 0.f;
    #pragma unroll
    for (int k = 0; k < 4; k++) { e[k] = __expf((lg[k] - m) * inv); sum += e[k]; }
    float r = 1.0f / sum;
    #pragma unroll
    for (int k = 0; k < 4; k++) g_gate[n*4 + k] = e[k] * r;
}

// ---------------- kernel 3: fused weights + tables + zero stats --------------
__global__ void prep_kernel(const float* __restrict__ W, const float* __restrict__ b,
                            const float* __restrict__ mask, const int* __restrict__ shift_in,
                            const int* __restrict__ shift_out) {
    int blk = blockIdx.x;
    int tid = threadIdx.x;
    if (blk < NN) {
        int n = blk;
        float g0 = g_gate[n*4+0], g1 = g_gate[n*4+1], g2 = g_gate[n*4+2], g3 = g_gate[n*4+3];
        for (int i = tid; i < CC*DD; i += 256)
            g_Wf[n*CC*DD + i] = g0*W[i] + g1*W[CC*DD + i] + g2*W[2*CC*DD + i] + g3*W[3*CC*DD + i];
        if (tid < DD)
            g_bf[n*DD + tid] = g0*b[tid] + g1*b[DD+tid] + g2*b[2*DD+tid] + g3*b[3*DD+tid];
    } else {
        for (int j = tid; j < CC*ATSTRIDE; j += 256) {
            int c_out = j / ATSTRIDE, v_out = j % ATSTRIDE;
            if (v_out < VV) {
                int src = shift_in[v_out*CC + c_out];
                int vp = src >> 6, cp = src & 63;          // C == 64
                g_tsrc[j] = (short)(cp * (TTILE*VV) + vp); // index into raw smem tile
                g_tm[j] = tanhf(mask[v_out*CC + c_out]) + 1.0f;
            } else {
                g_tsrc[j] = 0;
                g_tm[j] = 0.f;
            }
        }
        for (int f = tid; f < FEAT; f += 256) {
            g_sum[f] = 0.f; g_sumsq[f] = 0.f;
            int s = shift_out[f];
            g_inv[s] = (short)(f + (f >> 6));       // padded v*65+d offset
        }
    }
}

// ---------------- kernel 4: persistent pipelined GEMM + scatter + stats ------
// 1024 blocks; block = (n = bid>>3, q8 = bid&7); 4 tiles of 8 frames.
// 8 warps; warp w = frame w; lane l owns d-pair (2l, 2l+1), all 25 v.
#define RAW_F (CC*TTILE*VV)        // 12800
#define AT_F  (8*ATW)              // 13312
#define GEMM_SMEM_BYTES ((RAW_F + AT_F + DD)*4 + FEAT*2)

__global__ void __launch_bounds__(256, 2) gemm_kernel(const float* __restrict__ x0) {
    extern __shared__ float smem[];
    float* raw  = smem;                 // [c][t][v] 64 x 200
    float* Ats  = raw + RAW_F;          // 8 x [c][26]; aliased as scatter buf [v*65+d]
    float* bfs  = Ats + AT_F;           // [64]
    short* invs = (short*)(bfs + DD);   // [1600]

    int bid = blockIdx.x;
    int n   = bid >> 3;
    int q8  = bid & 7;
    int tid = threadIdx.x;
    int w = tid >> 5, l = tid & 31;

    { // block-start staging (covered by first loop-top sync)
        for (int f = tid; f < FEAT; f += 256) invs[f] = g_inv[f];
        if (tid < DD) bfs[tid] = g_bf[n*DD + tid];
    }

    const float* xbase = x0 + (size_t)n * CC * (TT*VV);

    // prefetch tile 0
    {
        const float* xb = xbase + (q8*32) * VV;
        #pragma unroll
        for (int k = 0; k < 13; k++) {
            int i = tid + k*256;
            if (i < RAW_F/4) {
                int c = i / 50, qq = i - c*50;
                cp_async16(raw + c*(TTILE*VV) + qq*4, xb + c*(TT*VV) + qq*4);
            }
        }
        CP_COMMIT();
    }

    int d0 = 2*l;
    float* At = Ats + w * ATW;
    const float* rw = raw + w * VV;
    const float* Wg = g_Wf + (size_t)n * (CC*DD) + d0;

    float rsum[7], rsq[7];
    #pragma unroll
    for (int k = 0; k < 7; k++) { rsum[k] = 0.f; rsq[k] = 0.f; }

    for (int it = 0; it < NTILES; it++) {
        int t0 = q8*32 + it*TTILE;
        CP_WAIT0();
        __syncthreads();                       // raw ready; prev epilogue consumed

        // gather + mask into transposed At[c][26] (tables from global, L1-hot)
        {
            const short* __restrict__ ts = g_tsrc;
            const float* __restrict__ tm = g_tm;
            #pragma unroll 4
            for (int j = l; j < ATW; j += 32) At[j] = rw[ts[j]] * tm[j];
        }
        __syncthreads();                       // raw now free

        // prefetch next tile (DMA overlaps compute)
        if (it + 1 < NTILES) {
            const float* xb = xbase + (t0 + TTILE) * VV;
            #pragma unroll
            for (int k = 0; k < 13; k++) {
                int i = tid + k*256;
                if (i < RAW_F/4) {
                    int c = i / 50, qq = i - c*50;
                    cp_async16(raw + c*(TTILE*VV) + qq*4, xb + c*(TT*VV) + qq*4);
                }
            }
            CP_COMMIT();
        }

        // ---- FFMA2 mainloop (weights from global, batched x8) ----
        u64 acc0[13], acc1[13];
        {
            float b0 = bfs[d0], b1 = bfs[d0+1];
            u64 bb0 = pack2(b0, b0), bb1 = pack2(b1, b1);
            #pragma unroll
            for (int vp = 0; vp < 13; vp++) { acc0[vp] = bb0; acc1[vp] = bb1; }
        }
        #pragma unroll
        for (int cb = 0; cb < CC; cb += 8) {
            float2 wv[8];
            #pragma unroll
            for (int i = 0; i < 8; i++) wv[i] = *(const float2*)(Wg + (cb+i)*DD);
            #pragma unroll
            for (int i = 0; i < 8; i++) {
                u64 s0 = pack2(wv[i].x, wv[i].x);
                u64 s1 = pack2(wv[i].y, wv[i].y);
                const u64* ar = (const u64*)(At + (cb+i)*ATSTRIDE);
                #pragma unroll
                for (int vp = 0; vp < 13; vp++) {
                    u64 a2 = ar[vp];
                    acc0[vp] = ffma2(a2, s0, acc0[vp]);
                    acc1[vp] = ffma2(a2, s1, acc1[vp]);
                }
            }
        }

        // ---- epilogue: scatter through inverse shift_out into own At region ---
        // (warp-synchronous: all mainloop reads of At precede these writes)
        #pragma unroll
        for (int vp = 0; vp < 13; vp++) {
            float a0, a1, c0, c1;
            unpack2(acc0[vp], a0, a1);
            unpack2(acc1[vp], c0, c1);
            int v = 2*vp;
            int sb = v*DD + d0;
            At[invs[sb]]     = a0;
            At[invs[sb + 1]] = c0;
            if (v + 1 < VV) {
                At[invs[sb + DD]]     = a1;
                At[invs[sb + DD + 1]] = c1;
            }
        }
        __syncthreads();                       // all z-tiles staged

        // stats: thread owns fixed f-slots, accumulate in registers
        #pragma unroll
        for (int k = 0; k < 7; k++) {
            int f = tid + k*256;
            if (f < FEAT) {
                int pa = f + (f >> 6);
                float s = 0.f, q = 0.f;
                #pragma unroll
                for (int w8 = 0; w8 < 8; w8++) {
                    float v = Ats[w8*ATW + pa];
                    s += v; q += v*v;
                }
                rsum[k] += s; rsq[k] += q;
            }
        }
        // transposed coalesced store to g_z [n][d][t][v]
        {
            float* zb = g_z + (size_t)n * (CC*TT*VV) + (size_t)t0 * VV;
            #pragma unroll
            for (int k = 0; k < 13; k++) {
                int qd = tid + k*256;              // quad id, 3200 total
                if (qd < 3200) {
                    int e = qd*4;
                    int d = e / 200;
                    int r = e - d*200;             // multiple of 4, <= 196
                    float4 o;
                    #pragma unroll
                    for (int j = 0; j < 4; j++) {
                        int rr = r + j;
                        int tlj = rr / 25;
                        int vj = rr - tlj*25;
                        ((float*)&o)[j] = Ats[tlj*ATW + vj*65 + d];
                    }
                    *(float4*)(zb + (size_t)d*(TT*VV) + r) = o;
                }
            }
        }
        // loop-top sync protects Ats reuse by next gather
    }
    __syncthreads();
    #pragma unroll
    for (int k = 0; k < 7; k++) {
        int f = tid + k*256;
        if (f < FEAT) {
            atomicAdd(&g_sum[f], rsum[k]);
            atomicAdd(&g_sumsq[f], rsq[k]);
        }
    }
}

// ---------------- kernel 5: finalize BN params (f-space, no indirection) -----
__global__ void finalize_kernel(const float* __restrict__ gamma,
                                const float* __restrict__ beta) {
    int f = blockIdx.x * 256 + threadIdx.x;
    if (f >= FEAT) return;
    const float invn = 1.0f / (float)ROWS;
    float mu = g_sum[f] * invn;
    float var = g_sumsq[f] * invn - mu * mu;
    float sc = gamma[f] * rsqrtf(var + 1e-5f);
    g_scale[f] = sc;
    g_bias[f] = beta[f] - mu * sc;
}

// ---------------- kernel 6: elementwise BN + residual + relu -----------------
// block = (n, d): 6400 contiguous elements; f = v*64+d, v = idx%25.
__global__ void __launch_bounds__(256) final_kernel(const float* __restrict__ x0,
                                                    float* __restrict__ out) {
    __shared__ float sc[VV], bi[VV];
    int b = blockIdx.x;
    int n = b >> 6, d = b & 63;
    int tid = threadIdx.x;
    if (tid < VV) {
        sc[tid] = g_scale[tid*DD + d];
        bi[tid] = g_bias[tid*DD + d];
    }
    __syncthreads();
    size_t base = (size_t)n * (CC*TT*VV) + (size_t)d * (TT*VV);
    const float4* zp = (const float4*)(g_z + base);
    const float4* xp = (const float4*)(x0 + base);
    float4* op = (float4*)(out + base);
    #pragma unroll
    for (int k = 0; k < 7; k++) {
        int q = tid + k*256;
        if (q < (TT*VV)/4) {
            int e = q*4;
            int v0 = e - (e/25)*25;
            float4 z = zp[q], x = xp[q], o;
            #pragma unroll
            for (int j = 0; j < 4; j++) {
                int v = v0 + j; if (v >= VV) v -= VV;
                float val = ((const float*)&z)[j] * sc[v] + bi[v] + ((const float*)&x)[j];
                ((float*)&o)[j] = val > 0.f ? val : 0.f;
            }
            op[q] = o;
        }
    }
}

// ---------------- launcher ---------------------------------------------------
extern "C" void kernel_launch(void* const* d_in, const int* in_sizes, int n_in,
                              void* d_out, int out_size) {
    const float* x0       = (const float*)d_in[0];
    const int*   epoch    = (const int*)  d_in[1];
    const float* fc1_w    = (const float*)d_in[2];
    const float* fc1_b    = (const float*)d_in[3];
    const float* fc2_w    = (const float*)d_in[4];
    const float* fc2_b    = (const float*)d_in[5];
    const float* W        = (const float*)d_in[6];
    const float* b        = (const float*)d_in[7];
    const float* mask     = (const float*)d_in[8];
    const float* gamma    = (const float*)d_in[9];
    const float* beta     = (const float*)d_in[10];
    const int*   shift_in = (const int*)  d_in[11];
    const int*   shift_out= (const int*)  d_in[12];
    float* out = (float*)d_out;

    cudaFuncSetAttribute(gemm_kernel, cudaFuncAttributeMaxDynamicSharedMemorySize, GEMM_SMEM_BYTES);

    pool_kernel<<<NN*CC, 256>>>(x0);
    gate_kernel<<<1, 128>>>(fc1_w, fc1_b, fc2_w, fc2_b, epoch);
    prep_kernel<<<NN + 1, 256>>>(W, b, mask, shift_in, shift_out);
    gemm_kernel<<<NN * 8, 256, GEMM_SMEM_BYTES>>>(x0);
    finalize_kernel<<<(FEAT + 255)/256, 256>>>(gamma, beta);
    final_kernel<<<NN * CC, 256>>>(x0, out);
}

// round 10
// speedup vs baseline: 1.5275x; 1.1325x over previous
#include <cuda_runtime.h>
#include <cstdint>

// Problem constants
#define NN 128
#define CC 64
#define TT 256
#define VV 25
#define DD 64
#define RR 16           // SE reduction dim (C/4)
#define FEAT 1600       // V*D
#define ROWS (NN*TT)    // 32768
#define TTILE 8         // t-frames per gemm tile
#define NTILES 4        // tiles per block
#define ATSTRIDE 28     // v-dim stride in At (112B rows, 16B-aligned for LDS.128)
#define ATW (CC*ATSTRIDE)   // 1792 floats per warp region

typedef unsigned long long u64;

// ---------------- scratch (device globals; no allocations allowed) ----------
__device__ float g_pooled[NN*CC];
__device__ float g_gate[NN*4];
__device__ float g_Wf[NN*CC*DD];      // 2 MB
__device__ float g_bf[NN*DD];
__device__ float g_z[(size_t)NN*CC*TT*VV]; // 209.7 MB, OUTPUT layout [n][d][t][v], pre-BN
__device__ float g_sum[FEAT];
__device__ float g_sumsq[FEAT];
__device__ float g_scale[FEAT];
__device__ float g_bias[FEAT];
__device__ float2 g_tpack[CC*ATSTRIDE]; // packed gather rec: {tm, bitcast(src)}
__device__ short g_inv[FEAT];           // inv_pad: s -> f+(f>>6)  (= v*65+d)

// ---------------- f32x2 helpers ---------------------------------------------
__device__ __forceinline__ u64 pack2(float lo, float hi) {
    u64 r; asm("mov.b64 %0, {%1, %2};" : "=l"(r) : "f"(lo), "f"(hi)); return r;
}
__device__ __forceinline__ void unpack2(u64 v, float& lo, float& hi) {
    asm("mov.b64 {%0, %1}, %2;" : "=f"(lo), "=f"(hi) : "l"(v));
}
__device__ __forceinline__ u64 ffma2(u64 a, u64 b, u64 c) {
    u64 d; asm("fma.rn.f32x2 %0, %1, %2, %3;" : "=l"(d) : "l"(a), "l"(b), "l"(c));
    return d;
}
__device__ __forceinline__ void cp_async16(float* dst_smem, const void* src) {
    unsigned d = (unsigned)__cvta_generic_to_shared(dst_smem);
    asm volatile("cp.async.cg.shared.global [%0], [%1], 16;" :: "r"(d), "l"(src));
}
#define CP_COMMIT() asm volatile("cp.async.commit_group;")
#define CP_WAIT0()  asm volatile("cp.async.wait_group 0;")

// ---------------- kernel 1: global average pool ------------------------------
__global__ void pool_kernel(const float* __restrict__ x0) {
    int nc = blockIdx.x;
    const float4* p = (const float4*)(x0 + (size_t)nc * (TT*VV));
    float s = 0.f;
    for (int i = threadIdx.x; i < (TT*VV)/4; i += 256) {
        float4 v = p[i];
        s += v.x + v.y + v.z + v.w;
    }
    for (int off = 16; off > 0; off >>= 1) s += __shfl_down_sync(0xffffffffu, s, off);
    __shared__ float red[8];
    int w = threadIdx.x >> 5, l = threadIdx.x & 31;
    if (l == 0) red[w] = s;
    __syncthreads();
    if (threadIdx.x == 0) {
        float t = 0.f;
        #pragma unroll
        for (int i = 0; i < 8; i++) t += red[i];
        g_pooled[nc] = t * (1.f / (TT*VV));
    }
}

// ---------------- kernel 2: SE gate ------------------------------------------
__global__ void gate_kernel(const float* __restrict__ fc1_w, const float* __restrict__ fc1_b,
                            const float* __restrict__ fc2_w, const float* __restrict__ fc2_b,
                            const int* __restrict__ epoch_p) {
    int n = threadIdx.x;
    if (n >= NN) return;
    float pooled[CC];
    #pragma unroll
    for (int c = 0; c < CC; c++) pooled[c] = g_pooled[n*CC + c];
    float h[RR];
    #pragma unroll
    for (int j = 0; j < RR; j++) {
        float s = fc1_b[j];
        #pragma unroll
        for (int c = 0; c < CC; c++) s += pooled[c] * fc1_w[j*CC + c];
        h[j] = s > 0.f ? s : 0.f;
    }
    float lg[4];
    #pragma unroll
    for (int k = 0; k < 4; k++) {
        float s = fc2_b[k];
        #pragma unroll
        for (int j = 0; j < RR; j++) s += h[j] * fc2_w[k*RR + j];
        lg[k] = s;
    }
    int ep = *epoch_p;
    float tao = (ep >= 60) ? 1.0f : (-(29.0f / 60.0f) * (float)ep + 30.0f);
    float inv = 1.0f / tao;
    float m = lg[0];
    #pragma unroll
    for (int k = 1; k < 4; k++) m = fmaxf(m, lg[k]);
    float e[4], sum = 0.f;
    #pragma unroll
    for (int k = 0; k < 4; k++) { e[k] = __expf((lg[k] - m) * inv); sum += e[k]; }
    float r = 1.0f / sum;
    #pragma unroll
    for (int k = 0; k < 4; k++) g_gate[n*4 + k] = e[k] * r;
}

// ---------------- kernel 3: fused weights + tables + zero stats --------------
__global__ void prep_kernel(const float* __restrict__ W, const float* __restrict__ b,
                            const float* __restrict__ mask, const int* __restrict__ shift_in,
                            const int* __restrict__ shift_out) {
    int blk = blockIdx.x;
    int tid = threadIdx.x;
    if (blk < NN) {
        int n = blk;
        float g0 = g_gate[n*4+0], g1 = g_gate[n*4+1], g2 = g_gate[n*4+2], g3 = g_gate[n*4+3];
        for (int i = tid; i < CC*DD; i += 256)
            g_Wf[n*CC*DD + i] = g0*W[i] + g1*W[CC*DD + i] + g2*W[2*CC*DD + i] + g3*W[3*CC*DD + i];
        if (tid < DD)
            g_bf[n*DD + tid] = g0*b[tid] + g1*b[DD+tid] + g2*b[2*DD+tid] + g3*b[3*DD+tid];
    } else {
        for (int j = tid; j < CC*ATSTRIDE; j += 256) {
            int c_out = j / ATSTRIDE, v_out = j % ATSTRIDE;
            float2 rec;
            if (v_out < VV) {
                int src = shift_in[v_out*CC + c_out];
                int vp = src >> 6, cp = src & 63;          // C == 64
                rec.x = tanhf(mask[v_out*CC + c_out]) + 1.0f;
                rec.y = __int_as_float(cp * (TTILE*VV) + vp);
            } else {
                rec.x = 0.f;
                rec.y = __int_as_float(0);
            }
            g_tpack[j] = rec;
        }
        for (int f = tid; f < FEAT; f += 256) {
            g_sum[f] = 0.f; g_sumsq[f] = 0.f;
            int s = shift_out[f];
            g_inv[s] = (short)(f + (f >> 6));       // padded v*65+d offset
        }
    }
}

// ---------------- kernel 4: persistent pipelined GEMM + scatter + stats ------
// 1024 blocks; block = (n = bid>>3, q8 = bid&7); 4 tiles of 8 frames.
// 8 warps; warp w = frame w; lane l owns d-pair (2l, 2l+1), all 25 v.
#define RAW_F (CC*TTILE*VV)        // 12800
#define AT_F  (8*ATW)              // 14336
#define GEMM_SMEM_BYTES ((RAW_F + AT_F + DD)*4 + FEAT*2)

__global__ void __launch_bounds__(256, 2) gemm_kernel(const float* __restrict__ x0) {
    extern __shared__ float smem[];
    float* raw  = smem;                 // [c][t][v] 64 x 200
    float* Ats  = raw + RAW_F;          // 8 x [c][28]; aliased as scatter buf [v*65+d]
    float* bfs  = Ats + AT_F;           // [64]
    short* invs = (short*)(bfs + DD);   // [1600]

    int bid = blockIdx.x;
    int n   = bid >> 3;
    int q8  = bid & 7;
    int tid = threadIdx.x;
    int w = tid >> 5, l = tid & 31;

    { // block-start staging (covered by first loop-top sync)
        for (int f = tid; f < FEAT; f += 256) invs[f] = g_inv[f];
        if (tid < DD) bfs[tid] = g_bf[n*DD + tid];
    }

    const float* xbase = x0 + (size_t)n * CC * (TT*VV);

    // prefetch tile 0
    {
        const float* xb = xbase + (q8*32) * VV;
        #pragma unroll
        for (int k = 0; k < 13; k++) {
            int i = tid + k*256;
            if (i < RAW_F/4) {
                int c = i / 50, qq = i - c*50;
                cp_async16(raw + c*(TTILE*VV) + qq*4, xb + c*(TT*VV) + qq*4);
            }
        }
        CP_COMMIT();
    }

    int d0 = 2*l;
    float* At = Ats + w * ATW;
    const float* rw = raw + w * VV;
    const float* Wg = g_Wf + (size_t)n * (CC*DD) + d0;

    float rsum[7], rsq[7];
    #pragma unroll
    for (int k = 0; k < 7; k++) { rsum[k] = 0.f; rsq[k] = 0.f; }

    for (int it = 0; it < NTILES; it++) {
        int t0 = q8*32 + it*TTILE;
        CP_WAIT0();
        __syncthreads();                       // raw ready; prev epilogue consumed

        // gather + mask into transposed At[c][28] (packed table: one LDG.64/elt)
        {
            const float2* __restrict__ tp = g_tpack;
            #pragma unroll 4
            for (int j = l; j < ATW; j += 32) {
                float2 rec = tp[j];
                At[j] = rw[__float_as_int(rec.y)] * rec.x;
            }
        }
        __syncthreads();                       // raw now free

        // prefetch next tile (DMA overlaps compute)
        if (it + 1 < NTILES) {
            const float* xb = xbase + (t0 + TTILE) * VV;
            #pragma unroll
            for (int k = 0; k < 13; k++) {
                int i = tid + k*256;
                if (i < RAW_F/4) {
                    int c = i / 50, qq = i - c*50;
                    cp_async16(raw + c*(TTILE*VV) + qq*4, xb + c*(TT*VV) + qq*4);
                }
            }
            CP_COMMIT();
        }

        // ---- FFMA2 mainloop (LDS.128 operand loads; weights from global L1) ----
        u64 acc0[13], acc1[13];
        {
            float b0 = bfs[d0], b1 = bfs[d0+1];
            u64 bb0 = pack2(b0, b0), bb1 = pack2(b1, b1);
            #pragma unroll
            for (int vp = 0; vp < 13; vp++) { acc0[vp] = bb0; acc1[vp] = bb1; }
        }
        #pragma unroll
        for (int cb = 0; cb < CC; cb += 8) {
            float2 wv[8];
            #pragma unroll
            for (int i = 0; i < 8; i++) wv[i] = *(const float2*)(Wg + (cb+i)*DD);
            #pragma unroll
            for (int i = 0; i < 8; i++) {
                u64 s0 = pack2(wv[i].x, wv[i].x);
                u64 s1 = pack2(wv[i].y, wv[i].y);
                const float* ar = At + (cb+i)*ATSTRIDE;
                #pragma unroll
                for (int p = 0; p < 6; p++) {
                    ulonglong2 a2 = ((const ulonglong2*)ar)[p];
                    acc0[2*p]   = ffma2(a2.x, s0, acc0[2*p]);
                    acc1[2*p]   = ffma2(a2.x, s1, acc1[2*p]);
                    acc0[2*p+1] = ffma2(a2.y, s0, acc0[2*p+1]);
                    acc1[2*p+1] = ffma2(a2.y, s1, acc1[2*p+1]);
                }
                u64 a12 = ((const u64*)ar)[12];
                acc0[12] = ffma2(a12, s0, acc0[12]);
                acc1[12] = ffma2(a12, s1, acc1[12]);
            }
        }

        // ---- epilogue: scatter through inverse shift_out into own At region ---
        // (warp-synchronous: all mainloop reads of At precede these writes)
        #pragma unroll
        for (int vp = 0; vp < 13; vp++) {
            float a0, a1, c0, c1;
            unpack2(acc0[vp], a0, a1);
            unpack2(acc1[vp], c0, c1);
            int v = 2*vp;
            int sb = v*DD + d0;
            At[invs[sb]]     = a0;
            At[invs[sb + 1]] = c0;
            if (v + 1 < VV) {
                At[invs[sb + DD]]     = a1;
                At[invs[sb + DD + 1]] = c1;
            }
        }
        __syncthreads();                       // all z-tiles staged

        // stats: thread owns fixed f-slots, accumulate in registers
        #pragma unroll
        for (int k = 0; k < 7; k++) {
            int f = tid + k*256;
            if (f < FEAT) {
                int pa = f + (f >> 6);
                float s = 0.f, q = 0.f;
                #pragma unroll
                for (int w8 = 0; w8 < 8; w8++) {
                    float v = Ats[w8*ATW + pa];
                    s += v; q += v*v;
                }
                rsum[k] += s; rsq[k] += q;
            }
        }
        // transposed coalesced store to g_z [n][d][t][v]
        {
            float* zb = g_z + (size_t)n * (CC*TT*VV) + (size_t)t0 * VV;
            #pragma unroll
            for (int k = 0; k < 13; k++) {
                int qd = tid + k*256;              // quad id, 3200 total
                if (qd < 3200) {
                    int e = qd*4;
                    int d = e / 200;
                    int r = e - d*200;             // multiple of 4, <= 196
                    float4 o;
                    #pragma unroll
                    for (int j = 0; j < 4; j++) {
                        int rr = r + j;
                        int tlj = rr / 25;
                        int vj = rr - tlj*25;
                        ((float*)&o)[j] = Ats[tlj*ATW + vj*65 + d];
                    }
                    *(float4*)(zb + (size_t)d*(TT*VV) + r) = o;
                }
            }
        }
        // loop-top sync protects Ats reuse by next gather
    }
    __syncthreads();
    #pragma unroll
    for (int k = 0; k < 7; k++) {
        int f = tid + k*256;
        if (f < FEAT) {
            atomicAdd(&g_sum[f], rsum[k]);
            atomicAdd(&g_sumsq[f], rsq[k]);
        }
    }
}

// ---------------- kernel 5: finalize BN params (f-space, no indirection) -----
__global__ void finalize_kernel(const float* __restrict__ gamma,
                                const float* __restrict__ beta) {
    int f = blockIdx.x * 256 + threadIdx.x;
    if (f >= FEAT) return;
    const float invn = 1.0f / (float)ROWS;
    float mu = g_sum[f] * invn;
    float var = g_sumsq[f] * invn - mu * mu;
    float sc = gamma[f] * rsqrtf(var + 1e-5f);
    g_scale[f] = sc;
    g_bias[f] = beta[f] - mu * sc;
}

// ---------------- kernel 6: elementwise BN + residual + relu -----------------
// block = (n, d): 6400 contiguous elements; f = v*64+d, v = idx%25.
__global__ void __launch_bounds__(256) final_kernel(const float* __restrict__ x0,
                                                    float* __restrict__ out) {
    __shared__ float sc[VV], bi[VV];
    int b = blockIdx.x;
    int n = b >> 6, d = b & 63;
    int tid = threadIdx.x;
    if (tid < VV) {
        sc[tid] = g_scale[tid*DD + d];
        bi[tid] = g_bias[tid*DD + d];
    }
    __syncthreads();
    size_t base = (size_t)n * (CC*TT*VV) + (size_t)d * (TT*VV);
    const float4* zp = (const float4*)(g_z + base);
    const float4* xp = (const float4*)(x0 + base);
    float4* op = (float4*)(out + base);
    #pragma unroll
    for (int k = 0; k < 7; k++) {
        int q = tid + k*256;
        if (q < (TT*VV)/4) {
            int e = q*4;
            int v0 = e - (e/25)*25;
            float4 z = zp[q], x = xp[q], o;
            #pragma unroll
            for (int j = 0; j < 4; j++) {
                int v = v0 + j; if (v >= VV) v -= VV;
                float val = ((const float*)&z)[j] * sc[v] + bi[v] + ((const float*)&x)[j];
                ((float*)&o)[j] = val > 0.f ? val : 0.f;
            }
            op[q] = o;
        }
    }
}

// ---------------- launcher ---------------------------------------------------
extern "C" void kernel_launch(void* const* d_in, const int* in_sizes, int n_in,
                              void* d_out, int out_size) {
    const float* x0       = (const float*)d_in[0];
    const int*   epoch    = (const int*)  d_in[1];
    const float* fc1_w    = (const float*)d_in[2];
    const float* fc1_b    = (const float*)d_in[3];
    const float* fc2_w    = (const float*)d_in[4];
    const float* fc2_b    = (const float*)d_in[5];
    const float* W        = (const float*)d_in[6];
    const float* b        = (const float*)d_in[7];
    const float* mask     = (const float*)d_in[8];
    const float* gamma    = (const float*)d_in[9];
    const float* beta     = (const float*)d_in[10];
    const int*   shift_in = (const int*)  d_in[11];
    const int*   shift_out= (const int*)  d_in[12];
    float* out = (float*)d_out;

    cudaFuncSetAttribute(gemm_kernel, cudaFuncAttributeMaxDynamicSharedMemorySize, GEMM_SMEM_BYTES);

    pool_kernel<<<NN*CC, 256>>>(x0);
    gate_kernel<<<1, 128>>>(fc1_w, fc1_b, fc2_w, fc2_b, epoch);
    prep_kernel<<<NN + 1, 256>>>(W, b, mask, shift_in, shift_out);
    gemm_kernel<<<NN * 8, 256, GEMM_SMEM_BYTES>>>(x0);
    finalize_kernel<<<(FEAT + 255)/256, 256>>>(gamma, beta);
    final_kernel<<<NN * CC, 256>>>(x0, out);
}